// round 5
// baseline (speedup 1.0000x reference)
#include <cuda_runtime.h>

// Problem constants
constexpr int B  = 2;
constexpr int S  = 2048;
constexpr int D  = 512;
constexpr int H  = 8;
constexpr int DK = 64;           // D / H

// Scratch (allocation-free rule: __device__ globals)
__device__ float g_Q[B * H * S * DK];   // [B,H,S,DK]
__device__ float g_K[B * H * S * DK];
__device__ float g_V[B * H * S * DK];
__device__ float g_X[B * S * D];        // attention output, [B,S,D]

// ---------------------------------------------------------------------------
// GEMM: out[m,n] = sum_k A[m,k] * W[n,k]   (A: [4096,512], W: [512,512])
// 64x64 tile, BK=32, 256 threads, 4x4 frags. SPLIT writes head-split layout.
// ---------------------------------------------------------------------------

__global__ __launch_bounds__(256) void proj_qkv_kernel(
    const float* __restrict__ qin, const float* __restrict__ kin,
    const float* __restrict__ vin, const float* __restrict__ W)
{
    const float* A;
    float* out;
    if (blockIdx.z == 0)      { A = qin; out = g_Q; }
    else if (blockIdx.z == 1) { A = kin; out = g_K; }
    else                      { A = vin; out = g_V; }

    __shared__ float As[32][68];   // [k][m]
    __shared__ float Bs[32][68];   // [k][n]

    const int tid = threadIdx.x;
    const int ty = tid >> 4;       // 0..15  -> rows ty*4..+3
    const int tx = tid & 15;       // 0..15  -> cols tx*4..+3
    const int m0 = blockIdx.y * 64;
    const int n0 = blockIdx.x * 64;

    float acc[4][4] = {};

    for (int kt = 0; kt < D; kt += 32) {
        // load tiles (transposed into smem)
        #pragma unroll
        for (int q2 = 0; q2 < 2; q2++) {
            int id = tid * 2 + q2;       // 0..511
            int m  = id >> 3;            // 0..63
            int kq = (id & 7) * 4;       // 0..28
            float4 fa = *(const float4*)&A[(m0 + m) * D + kt + kq];
            As[kq + 0][m] = fa.x; As[kq + 1][m] = fa.y;
            As[kq + 2][m] = fa.z; As[kq + 3][m] = fa.w;
            float4 fb = *(const float4*)&W[(n0 + m) * D + kt + kq];
            Bs[kq + 0][m] = fb.x; Bs[kq + 1][m] = fb.y;
            Bs[kq + 2][m] = fb.z; Bs[kq + 3][m] = fb.w;
        }
        __syncthreads();

        #pragma unroll 8
        for (int kk = 0; kk < 32; kk++) {
            float4 af = *(const float4*)&As[kk][ty * 4];
            float4 bf = *(const float4*)&Bs[kk][tx * 4];
            float av[4] = {af.x, af.y, af.z, af.w};
            float bv[4] = {bf.x, bf.y, bf.z, bf.w};
            #pragma unroll
            for (int i = 0; i < 4; i++)
                #pragma unroll
                for (int j = 0; j < 4; j++)
                    acc[i][j] = fmaf(av[i], bv[j], acc[i][j]);
        }
        __syncthreads();
    }

    // write head-split: out[((b*H + h)*S + s)*DK + dk]
    const int h = n0 >> 6;           // n0 multiple of 64 -> fixed head
    #pragma unroll
    for (int i = 0; i < 4; i++) {
        int m = m0 + ty * 4 + i;
        int b = m >> 11;             // m / 2048
        int s = m & 2047;
        float4 r = make_float4(acc[i][0], acc[i][1], acc[i][2], acc[i][3]);
        *(float4*)&out[(((b * H + h) * S) + s) * DK + tx * 4] = r;
    }
}

__global__ __launch_bounds__(256) void proj_out_kernel(
    const float* __restrict__ W, float* __restrict__ out)
{
    __shared__ float As[32][68];
    __shared__ float Bs[32][68];

    const int tid = threadIdx.x;
    const int ty = tid >> 4;
    const int tx = tid & 15;
    const int m0 = blockIdx.y * 64;
    const int n0 = blockIdx.x * 64;

    float acc[4][4] = {};

    for (int kt = 0; kt < D; kt += 32) {
        #pragma unroll
        for (int q2 = 0; q2 < 2; q2++) {
            int id = tid * 2 + q2;
            int m  = id >> 3;
            int kq = (id & 7) * 4;
            float4 fa = *(const float4*)&g_X[(m0 + m) * D + kt + kq];
            As[kq + 0][m] = fa.x; As[kq + 1][m] = fa.y;
            As[kq + 2][m] = fa.z; As[kq + 3][m] = fa.w;
            float4 fb = *(const float4*)&W[(n0 + m) * D + kt + kq];
            Bs[kq + 0][m] = fb.x; Bs[kq + 1][m] = fb.y;
            Bs[kq + 2][m] = fb.z; Bs[kq + 3][m] = fb.w;
        }
        __syncthreads();

        #pragma unroll 8
        for (int kk = 0; kk < 32; kk++) {
            float4 af = *(const float4*)&As[kk][ty * 4];
            float4 bf = *(const float4*)&Bs[kk][tx * 4];
            float av[4] = {af.x, af.y, af.z, af.w};
            float bv[4] = {bf.x, bf.y, bf.z, bf.w};
            #pragma unroll
            for (int i = 0; i < 4; i++)
                #pragma unroll
                for (int j = 0; j < 4; j++)
                    acc[i][j] = fmaf(av[i], bv[j], acc[i][j]);
        }
        __syncthreads();
    }

    #pragma unroll
    for (int i = 0; i < 4; i++) {
        int m = m0 + ty * 4 + i;
        float4 r = make_float4(acc[i][0], acc[i][1], acc[i][2], acc[i][3]);
        *(float4*)&out[m * D + n0 + tx * 4] = r;
    }
}

// ---------------------------------------------------------------------------
// Attention: per (b,h) and 64-row q-tile, stream 64-wide K/V tiles with
// online softmax. mask==0 -> score := 1e-9 (pre-softmax, NOT -inf).
// ---------------------------------------------------------------------------

__global__ __launch_bounds__(256, 2) void attn_kernel(const int* __restrict__ mask)
{
    const int q0 = blockIdx.x * 64;
    const int bh = blockIdx.y;                 // b*H + h
    const float* Qp = g_Q + (size_t)bh * S * DK;
    const float* Kp = g_K + (size_t)bh * S * DK;
    const float* Vp = g_V + (size_t)bh * S * DK;

    __shared__ float Qst[64][68];  // [d][r]
    __shared__ float Kst[64][68];  // [d][c]
    __shared__ float Vs [64][68];  // [k][dv]
    __shared__ float Ps [64][68];  // [r][c]

    const int tid = threadIdx.x;
    const int ty = tid >> 4;       // rows ty*4..+3
    const int tx = tid & 15;       // cols tx*4..+3
    const int ty4 = ty * 4, tx4 = tx * 4;

    // load Q tile transposed
    {
        int r  = tid >> 2;
        int dq = (tid & 3) * 16;
        #pragma unroll
        for (int l = 0; l < 4; l++) {
            float4 f = *(const float4*)&Qp[(q0 + r) * DK + dq + l * 4];
            Qst[dq + l * 4 + 0][r] = f.x; Qst[dq + l * 4 + 1][r] = f.y;
            Qst[dq + l * 4 + 2][r] = f.z; Qst[dq + l * 4 + 3][r] = f.w;
        }
    }

    float o[4][4] = {};
    float rmax[4], rsum[4];
    #pragma unroll
    for (int i = 0; i < 4; i++) { rmax[i] = -1e30f; rsum[i] = 0.f; }

    for (int k0 = 0; k0 < S; k0 += 64) {
        __syncthreads();   // prior-iteration consumers done (also covers Q load)
        {
            int r  = tid >> 2;
            int dq = (tid & 3) * 16;
            #pragma unroll
            for (int l = 0; l < 4; l++) {
                float4 f = *(const float4*)&Kp[(k0 + r) * DK + dq + l * 4];
                Kst[dq + l * 4 + 0][r] = f.x; Kst[dq + l * 4 + 1][r] = f.y;
                Kst[dq + l * 4 + 2][r] = f.z; Kst[dq + l * 4 + 3][r] = f.w;
                float4 g = *(const float4*)&Vp[(k0 + r) * DK + dq + l * 4];
                *(float4*)&Vs[r][dq + l * 4] = g;
            }
        }
        __syncthreads();

        // scores tile: acc[i][j] = Q[r,:] . K[c,:]
        float acc[4][4] = {};
        #pragma unroll 16
        for (int d = 0; d < 64; d++) {
            float4 af = *(const float4*)&Qst[d][ty4];
            float4 bf = *(const float4*)&Kst[d][tx4];
            float av[4] = {af.x, af.y, af.z, af.w};
            float bv[4] = {bf.x, bf.y, bf.z, bf.w};
            #pragma unroll
            for (int i = 0; i < 4; i++)
                #pragma unroll
                for (int j = 0; j < 4; j++)
                    acc[i][j] = fmaf(av[i], bv[j], acc[i][j]);
        }

        // scale + mask + online softmax (per local row i; 16 lanes own a row)
        #pragma unroll
        for (int i = 0; i < 4; i++) {
            int gq = q0 + ty4 + i;
            int4 mr = *(const int4*)&mask[(size_t)gq * S + k0 + tx4];
            float sc[4];
            sc[0] = (mr.x == 0) ? 1e-9f : acc[i][0] * 0.125f;
            sc[1] = (mr.y == 0) ? 1e-9f : acc[i][1] * 0.125f;
            sc[2] = (mr.z == 0) ? 1e-9f : acc[i][2] * 0.125f;
            sc[3] = (mr.w == 0) ? 1e-9f : acc[i][3] * 0.125f;

            float tmax = fmaxf(fmaxf(sc[0], sc[1]), fmaxf(sc[2], sc[3]));
            #pragma unroll
            for (int off = 8; off > 0; off >>= 1)
                tmax = fmaxf(tmax, __shfl_xor_sync(0xffffffffu, tmax, off));

            float nm   = fmaxf(rmax[i], tmax);
            float corr = __expf(rmax[i] - nm);
            rmax[i] = nm;

            float p0 = __expf(sc[0] - nm);
            float p1 = __expf(sc[1] - nm);
            float p2 = __expf(sc[2] - nm);
            float p3 = __expf(sc[3] - nm);
            float ts = (p0 + p1) + (p2 + p3);
            #pragma unroll
            for (int off = 8; off > 0; off >>= 1)
                ts += __shfl_xor_sync(0xffffffffu, ts, off);

            rsum[i] = rsum[i] * corr + ts;
            #pragma unroll
            for (int j = 0; j < 4; j++) o[i][j] *= corr;

            *(float4*)&Ps[ty4 + i][tx4] = make_float4(p0, p1, p2, p3);
        }
        __syncthreads();

        // O += P * V
        #pragma unroll 16
        for (int kk = 0; kk < 64; kk++) {
            float4 bf = *(const float4*)&Vs[kk][tx4];
            float bv[4] = {bf.x, bf.y, bf.z, bf.w};
            float av[4];
            #pragma unroll
            for (int i = 0; i < 4; i++) av[i] = Ps[ty4 + i][kk];
            #pragma unroll
            for (int i = 0; i < 4; i++)
                #pragma unroll
                for (int j = 0; j < 4; j++)
                    o[i][j] = fmaf(av[i], bv[j], o[i][j]);
        }
    }

    // normalize and write back to [B,S,D]
    const int b = bh >> 3;
    const int h = bh & 7;
    #pragma unroll
    for (int i = 0; i < 4; i++) {
        float inv = 1.f / rsum[i];
        int s = q0 + ty4 + i;
        float4 r = make_float4(o[i][0] * inv, o[i][1] * inv,
                               o[i][2] * inv, o[i][3] * inv);
        *(float4*)&g_X[((size_t)b * S + s) * D + h * DK + tx4] = r;
    }
}

// ---------------------------------------------------------------------------

extern "C" void kernel_launch(void* const* d_in, const int* in_sizes, int n_in,
                              void* d_out, int out_size)
{
    const float* q    = (const float*)d_in[0];
    const float* k    = (const float*)d_in[1];
    const float* v    = (const float*)d_in[2];
    const int*   mask = (const int*)d_in[3];
    const float* Wq   = (const float*)d_in[4];
    const float* Wo   = (const float*)d_in[5];
    float* out = (float*)d_out;

    proj_qkv_kernel<<<dim3(D / 64, (B * S) / 64, 3), 256>>>(q, k, v, Wq);
    attn_kernel<<<dim3(S / 64, B * H), 256>>>(mask);
    proj_out_kernel<<<dim3(D / 64, (B * S) / 64), 256>>>(Wo, out);
}

// round 6
// speedup vs baseline: 2.5492x; 2.5492x over previous
#include <cuda_runtime.h>
#include <cstdint>

// Problem constants
constexpr int B  = 2;
constexpr int S  = 2048;
constexpr int D  = 512;
constexpr int H  = 8;
constexpr int DK = 64;           // D / H

// Scratch (allocation-free rule: __device__ globals)
__device__ float g_Q[B * H * S * DK];   // [B,H,S,DK]
__device__ float g_K[B * H * S * DK];
__device__ float g_V[B * H * S * DK];
__device__ float g_X[B * S * D];        // attention output, [B,S,D]

// ---------------------------------------------------------------------------
// Helpers: tf32 conversion + m16n8k8 tf32 mma
// ---------------------------------------------------------------------------

__device__ __forceinline__ float to_tf32(float x) {
    asm("cvt.rna.tf32.f32 %0, %0;" : "+f"(x));
    return x;
}
__device__ __forceinline__ float4 cvt4(float4 f) {
    f.x = to_tf32(f.x); f.y = to_tf32(f.y);
    f.z = to_tf32(f.z); f.w = to_tf32(f.w);
    return f;
}
__device__ __forceinline__ uint32_t fbits(float x) { return __float_as_uint(x); }

__device__ __forceinline__ void mma_tf32(float4& c,
    uint32_t a0, uint32_t a1, uint32_t a2, uint32_t a3,
    uint32_t b0, uint32_t b1)
{
    asm volatile(
        "mma.sync.aligned.m16n8k8.row.col.f32.tf32.tf32.f32 "
        "{%0,%1,%2,%3},{%4,%5,%6,%7},{%8,%9},{%0,%1,%2,%3};"
        : "+f"(c.x), "+f"(c.y), "+f"(c.z), "+f"(c.w)
        : "r"(a0), "r"(a1), "r"(a2), "r"(a3), "r"(b0), "r"(b1));
}

// ---------------------------------------------------------------------------
// Projection GEMM (tensor-core tf32): out[m,n] = sum_k A[m,k] * W[n,k]
// Block tile 128x64, BK=32, 8 warps (4m x 2n), warp tile 32x32.
// ---------------------------------------------------------------------------

__global__ __launch_bounds__(256) void proj_qkv_kernel(
    const float* __restrict__ qin, const float* __restrict__ kin,
    const float* __restrict__ vin, const float* __restrict__ W)
{
    const float* A;
    float* out;
    if (blockIdx.z == 0)      { A = qin; out = g_Q; }
    else if (blockIdx.z == 1) { A = kin; out = g_K; }
    else                      { A = vin; out = g_V; }

    __shared__ float As[128][36];   // [m][k], stride 36 (==4 mod 32 -> conflict-free)
    __shared__ float Bs[64][36];    // [n][k]

    const int tid  = threadIdx.x;
    const int lane = tid & 31;
    const int warp = tid >> 5;
    const int g = lane >> 2;        // group 0..7
    const int t = lane & 3;         // thread-in-group
    const int wm = warp >> 1;       // 0..3
    const int wn = warp & 1;        // 0..1
    const int m0 = blockIdx.y * 128;
    const int n0 = blockIdx.x * 64;

    float4 c[2][4] = {};            // [m16 tile][n8 tile]

    for (int kt = 0; kt < D; kt += 32) {
        if (kt) __syncthreads();
        // stage A (128x32) and W (64x32), tf32-rounded
        #pragma unroll
        for (int q = 0; q < 4; q++) {
            int id = tid + q * 256;       // 0..1023
            int row = id >> 3;            // 0..127
            int kq = (id & 7) * 4;
            float4 f = cvt4(*(const float4*)&A[(size_t)(m0 + row) * D + kt + kq]);
            *(float4*)&As[row][kq] = f;
        }
        #pragma unroll
        for (int q = 0; q < 2; q++) {
            int id = tid + q * 256;       // 0..511
            int row = id >> 3;            // 0..63
            int kq = (id & 7) * 4;
            float4 f = cvt4(*(const float4*)&W[(size_t)(n0 + row) * D + kt + kq]);
            *(float4*)&Bs[row][kq] = f;
        }
        __syncthreads();

        #pragma unroll
        for (int ks = 0; ks < 4; ks++) {
            const int k0 = ks * 8;
            uint32_t a[2][4];
            #pragma unroll
            for (int i = 0; i < 2; i++) {
                int r = wm * 32 + i * 16;
                a[i][0] = fbits(As[r + g    ][k0 + t    ]);
                a[i][1] = fbits(As[r + g + 8][k0 + t    ]);
                a[i][2] = fbits(As[r + g    ][k0 + t + 4]);
                a[i][3] = fbits(As[r + g + 8][k0 + t + 4]);
            }
            #pragma unroll
            for (int j = 0; j < 4; j++) {
                int n = wn * 32 + j * 8 + g;
                uint32_t b0 = fbits(Bs[n][k0 + t    ]);
                uint32_t b1 = fbits(Bs[n][k0 + t + 4]);
                #pragma unroll
                for (int i = 0; i < 2; i++)
                    mma_tf32(c[i][j], a[i][0], a[i][1], a[i][2], a[i][3], b0, b1);
            }
        }
    }

    // epilogue: head-split write out[((b*H+h)*S+s)*DK + dk]
    const int h = n0 >> 6;
    #pragma unroll
    for (int i = 0; i < 2; i++) {
        int r0 = m0 + wm * 32 + i * 16 + g;
        int r1 = r0 + 8;
        int b0i = r0 >> 11, s0 = r0 & 2047;
        int b1i = r1 >> 11, s1 = r1 & 2047;
        #pragma unroll
        for (int j = 0; j < 4; j++) {
            int dk = (wn * 32 + j * 8 + 2 * t);
            float2 lo = make_float2(c[i][j].x, c[i][j].y);
            float2 hi = make_float2(c[i][j].z, c[i][j].w);
            *(float2*)&out[(((size_t)(b0i * H + h) * S) + s0) * DK + dk] = lo;
            *(float2*)&out[(((size_t)(b1i * H + h) * S) + s1) * DK + dk] = hi;
        }
    }
}

__global__ __launch_bounds__(256) void proj_out_kernel(
    const float* __restrict__ W, float* __restrict__ out)
{
    __shared__ float As[128][36];
    __shared__ float Bs[64][36];

    const int tid  = threadIdx.x;
    const int lane = tid & 31;
    const int warp = tid >> 5;
    const int g = lane >> 2;
    const int t = lane & 3;
    const int wm = warp >> 1;
    const int wn = warp & 1;
    const int m0 = blockIdx.y * 128;
    const int n0 = blockIdx.x * 64;

    float4 c[2][4] = {};

    for (int kt = 0; kt < D; kt += 32) {
        if (kt) __syncthreads();
        #pragma unroll
        for (int q = 0; q < 4; q++) {
            int id = tid + q * 256;
            int row = id >> 3;
            int kq = (id & 7) * 4;
            float4 f = cvt4(*(const float4*)&g_X[(size_t)(m0 + row) * D + kt + kq]);
            *(float4*)&As[row][kq] = f;
        }
        #pragma unroll
        for (int q = 0; q < 2; q++) {
            int id = tid + q * 256;
            int row = id >> 3;
            int kq = (id & 7) * 4;
            float4 f = cvt4(*(const float4*)&W[(size_t)(n0 + row) * D + kt + kq]);
            *(float4*)&Bs[row][kq] = f;
        }
        __syncthreads();

        #pragma unroll
        for (int ks = 0; ks < 4; ks++) {
            const int k0 = ks * 8;
            uint32_t a[2][4];
            #pragma unroll
            for (int i = 0; i < 2; i++) {
                int r = wm * 32 + i * 16;
                a[i][0] = fbits(As[r + g    ][k0 + t    ]);
                a[i][1] = fbits(As[r + g + 8][k0 + t    ]);
                a[i][2] = fbits(As[r + g    ][k0 + t + 4]);
                a[i][3] = fbits(As[r + g + 8][k0 + t + 4]);
            }
            #pragma unroll
            for (int j = 0; j < 4; j++) {
                int n = wn * 32 + j * 8 + g;
                uint32_t b0 = fbits(Bs[n][k0 + t    ]);
                uint32_t b1 = fbits(Bs[n][k0 + t + 4]);
                #pragma unroll
                for (int i = 0; i < 2; i++)
                    mma_tf32(c[i][j], a[i][0], a[i][1], a[i][2], a[i][3], b0, b1);
            }
        }
    }

    #pragma unroll
    for (int i = 0; i < 2; i++) {
        int r0 = m0 + wm * 32 + i * 16 + g;
        int r1 = r0 + 8;
        #pragma unroll
        for (int j = 0; j < 4; j++) {
            int n = n0 + wn * 32 + j * 8 + 2 * t;
            *(float2*)&out[(size_t)r0 * D + n] = make_float2(c[i][j].x, c[i][j].y);
            *(float2*)&out[(size_t)r1 * D + n] = make_float2(c[i][j].z, c[i][j].w);
        }
    }
}

// ---------------------------------------------------------------------------
// Attention (tensor-core tf32): 64 q-rows per block, 64-key chunks, online
// softmax. mask==0 -> score := 1e-9 (pre-softmax, NOT -inf).
// 8 warps: wm=warp>>1 owns 16 rows, wn=warp&1 owns 32 cols.
// Dynamic smem ~72.4 KB.
// ---------------------------------------------------------------------------

// float offsets into dynamic smem
constexpr int OFF_Q    = 0;            // [64][68]
constexpr int OFF_K    = 4352;         // [64][68]
constexpr int OFF_P    = 8704;         // [64][68]
constexpr int OFF_V    = 13056;        // [64][72]  (stride 72 == 8 mod 32)
constexpr int OFF_PMAX = 17664;        // [64][2]
constexpr int OFF_PSUM = 17792;        // [64][2]
constexpr int OFF_RMAX = 17920;        // [64]
constexpr int OFF_RSUM = 17984;        // [64]
constexpr int OFF_CORR = 18048;        // [64]
constexpr int ATT_SMEM_FLOATS = 18112;
constexpr int ATT_SMEM_BYTES  = ATT_SMEM_FLOATS * 4;   // 72448

__global__ __launch_bounds__(256) void attn_kernel(const int* __restrict__ mask)
{
    extern __shared__ float sm[];
    float* Qs    = sm + OFF_Q;
    float* Ks    = sm + OFF_K;
    float* Ps    = sm + OFF_P;
    float* Vs    = sm + OFF_V;
    float* pmax  = sm + OFF_PMAX;
    float* psum  = sm + OFF_PSUM;
    float* rmaxs = sm + OFF_RMAX;
    float* rsums = sm + OFF_RSUM;
    float* corrs = sm + OFF_CORR;

    const int q0 = blockIdx.x * 64;
    const int bh = blockIdx.y;
    const float* Qp = g_Q + (size_t)bh * S * DK;
    const float* Kp = g_K + (size_t)bh * S * DK;
    const float* Vp = g_V + (size_t)bh * S * DK;

    const int tid  = threadIdx.x;
    const int lane = tid & 31;
    const int warp = tid >> 5;
    const int g = lane >> 2;
    const int t = lane & 3;
    const int wm = warp >> 1;       // 0..3
    const int wn = warp & 1;        // 0..1
    const int r0l = wm * 16 + g;    // local q row (and +8)
    const int r1l = r0l + 8;
    const int colb = wn * 32;       // local column base (keys / dv)

    // stage Q (tf32) + init row stats
    #pragma unroll
    for (int q = 0; q < 4; q++) {
        int id = tid + q * 256;     // 0..1023
        int row = id >> 4;          // 0..63
        int c4 = (id & 15) * 4;
        float4 f = cvt4(*(const float4*)&Qp[(size_t)(q0 + row) * DK + c4]);
        *(float4*)&Qs[row * 68 + c4] = f;
    }
    if (tid < 64) { rmaxs[tid] = -1e30f; rsums[tid] = 0.f; }

    float4 o[4] = {};

    for (int k0 = 0; k0 < S; k0 += 64) {
        __syncthreads();   // prev PV + rsum update done; also covers Q/init
        // stage K,V chunk
        #pragma unroll
        for (int q = 0; q < 4; q++) {
            int id = tid + q * 256;
            int row = id >> 4;
            int c4 = (id & 15) * 4;
            float4 fk = cvt4(*(const float4*)&Kp[(size_t)(k0 + row) * DK + c4]);
            *(float4*)&Ks[row * 68 + c4] = fk;
            float4 fv = cvt4(*(const float4*)&Vp[(size_t)(k0 + row) * DK + c4]);
            *(float4*)&Vs[row * 72 + c4] = fv;
        }
        __syncthreads();

        // scores: S = Q @ K^T  (warp: 16 rows x 32 cols)
        float4 sc[4] = {};
        #pragma unroll
        for (int ks = 0; ks < 8; ks++) {
            const int d0 = ks * 8;
            uint32_t a0 = fbits(Qs[r0l * 68 + d0 + t    ]);
            uint32_t a1 = fbits(Qs[r1l * 68 + d0 + t    ]);
            uint32_t a2 = fbits(Qs[r0l * 68 + d0 + t + 4]);
            uint32_t a3 = fbits(Qs[r1l * 68 + d0 + t + 4]);
            #pragma unroll
            for (int j = 0; j < 4; j++) {
                int kc = colb + j * 8 + g;
                uint32_t b0 = fbits(Ks[kc * 68 + d0 + t    ]);
                uint32_t b1 = fbits(Ks[kc * 68 + d0 + t + 4]);
                mma_tf32(sc[j], a0, a1, a2, a3, b0, b1);
            }
        }

        // scale + mask
        const int gr0 = q0 + r0l, gr1 = q0 + r1l;
        #pragma unroll
        for (int j = 0; j < 4; j++) {
            int gc = k0 + colb + j * 8 + 2 * t;
            int2 mr0 = *(const int2*)&mask[(size_t)gr0 * S + gc];
            int2 mr1 = *(const int2*)&mask[(size_t)gr1 * S + gc];
            sc[j].x = mr0.x ? sc[j].x * 0.125f : 1e-9f;
            sc[j].y = mr0.y ? sc[j].y * 0.125f : 1e-9f;
            sc[j].z = mr1.x ? sc[j].z * 0.125f : 1e-9f;
            sc[j].w = mr1.y ? sc[j].w * 0.125f : 1e-9f;
        }

        // partial row max over this warp's 32 cols
        float pm0 = fmaxf(fmaxf(sc[0].x, sc[0].y), fmaxf(sc[1].x, sc[1].y));
        pm0 = fmaxf(pm0, fmaxf(fmaxf(sc[2].x, sc[2].y), fmaxf(sc[3].x, sc[3].y)));
        float pm1 = fmaxf(fmaxf(sc[0].z, sc[0].w), fmaxf(sc[1].z, sc[1].w));
        pm1 = fmaxf(pm1, fmaxf(fmaxf(sc[2].z, sc[2].w), fmaxf(sc[3].z, sc[3].w)));
        pm0 = fmaxf(pm0, __shfl_xor_sync(0xffffffffu, pm0, 1));
        pm0 = fmaxf(pm0, __shfl_xor_sync(0xffffffffu, pm0, 2));
        pm1 = fmaxf(pm1, __shfl_xor_sync(0xffffffffu, pm1, 1));
        pm1 = fmaxf(pm1, __shfl_xor_sync(0xffffffffu, pm1, 2));
        if (t == 0) {
            pmax[r0l * 2 + wn] = pm0;
            pmax[r1l * 2 + wn] = pm1;
        }
        __syncthreads();

        if (tid < 64) {
            float mo = rmaxs[tid];
            float mn = fmaxf(mo, fmaxf(pmax[tid * 2], pmax[tid * 2 + 1]));
            float cr = __expf(mo - mn);
            rmaxs[tid] = mn;
            corrs[tid] = cr;
            rsums[tid] *= cr;
        }
        __syncthreads();

        // exp, store P (tf32), partial sums, rescale O
        const float mn0 = rmaxs[r0l], mn1 = rmaxs[r1l];
        const float cr0 = corrs[r0l], cr1 = corrs[r1l];
        float s0 = 0.f, s1 = 0.f;
        #pragma unroll
        for (int j = 0; j < 4; j++) {
            float p0 = __expf(sc[j].x - mn0);
            float p1 = __expf(sc[j].y - mn0);
            float p2 = __expf(sc[j].z - mn1);
            float p3 = __expf(sc[j].w - mn1);
            s0 += p0 + p1;
            s1 += p2 + p3;
            int cl = colb + j * 8 + 2 * t;
            *(float2*)&Ps[r0l * 68 + cl] = make_float2(to_tf32(p0), to_tf32(p1));
            *(float2*)&Ps[r1l * 68 + cl] = make_float2(to_tf32(p2), to_tf32(p3));
            o[j].x *= cr0; o[j].y *= cr0;
            o[j].z *= cr1; o[j].w *= cr1;
        }
        s0 += __shfl_xor_sync(0xffffffffu, s0, 1);
        s0 += __shfl_xor_sync(0xffffffffu, s0, 2);
        s1 += __shfl_xor_sync(0xffffffffu, s1, 1);
        s1 += __shfl_xor_sync(0xffffffffu, s1, 2);
        if (t == 0) {
            psum[r0l * 2 + wn] = s0;
            psum[r1l * 2 + wn] = s1;
        }
        __syncthreads();

        if (tid < 64) rsums[tid] += psum[tid * 2] + psum[tid * 2 + 1];

        // O += P @ V  (warp: 16 rows x 32 dv cols, k=64)
        #pragma unroll
        for (int ks = 0; ks < 8; ks++) {
            const int kk = ks * 8;
            uint32_t a0 = fbits(Ps[r0l * 68 + kk + t    ]);
            uint32_t a1 = fbits(Ps[r1l * 68 + kk + t    ]);
            uint32_t a2 = fbits(Ps[r0l * 68 + kk + t + 4]);
            uint32_t a3 = fbits(Ps[r1l * 68 + kk + t + 4]);
            #pragma unroll
            for (int j = 0; j < 4; j++) {
                int dv = colb + j * 8 + g;
                uint32_t b0 = fbits(Vs[(kk + t    ) * 72 + dv]);
                uint32_t b1 = fbits(Vs[(kk + t + 4) * 72 + dv]);
                mma_tf32(o[j], a0, a1, a2, a3, b0, b1);
            }
        }
    }

    __syncthreads();   // final rsums update visible
    const float inv0 = 1.f / rsums[r0l];
    const float inv1 = 1.f / rsums[r1l];
    const int b = bh >> 3;
    const int h = bh & 7;
    #pragma unroll
    for (int j = 0; j < 4; j++) {
        int cl = colb + j * 8 + 2 * t;
        *(float2*)&g_X[((size_t)(b * S + q0 + r0l)) * D + h * 64 + cl] =
            make_float2(o[j].x * inv0, o[j].y * inv0);
        *(float2*)&g_X[((size_t)(b * S + q0 + r1l)) * D + h * 64 + cl] =
            make_float2(o[j].z * inv1, o[j].w * inv1);
    }
}

// ---------------------------------------------------------------------------

extern "C" void kernel_launch(void* const* d_in, const int* in_sizes, int n_in,
                              void* d_out, int out_size)
{
    const float* q    = (const float*)d_in[0];
    const float* k    = (const float*)d_in[1];
    const float* v    = (const float*)d_in[2];
    const int*   mask = (const int*)d_in[3];
    const float* Wq   = (const float*)d_in[4];
    const float* Wo   = (const float*)d_in[5];
    float* out = (float*)d_out;

    cudaFuncSetAttribute(attn_kernel,
                         cudaFuncAttributeMaxDynamicSharedMemorySize,
                         ATT_SMEM_BYTES);

    proj_qkv_kernel<<<dim3(D / 64, (B * S) / 128, 3), 256>>>(q, k, v, Wq);
    attn_kernel<<<dim3(S / 64, B * H), 256, ATT_SMEM_BYTES>>>(mask);
    proj_out_kernel<<<dim3(D / 64, (B * S) / 128), 256>>>(Wo, out);
}